// round 15
// baseline (speedup 1.0000x reference)
#include <cuda_runtime.h>
#include <cuda_fp16.h>

#define N_NODES_MAX 50000
#define N_EDGES_MAX 800000
#define NODE_ROW 128          // 4*MUL floats per node
#define OUT_ROW 256           // output floats per node
#define TABLE_N 256
#define XMIN (-8.0f)
#define XMAX (8.0f)
#define INV_SQRT3 0.57735026918962576f
#define OUT_SCALE 0.25f       // 1/sqrt(16)
#define SCAN_B 1024
#define MAX_SCAN_BLOCKS 64
#define CHUNK 128             // edges per warp in aggregate (single-wave grid)

// ---- static device scratch (no allocations allowed) ----
__device__ uint4  g_tab[TABLE_N * 32];          // per (i0,lane): 4 fp16 vals + 4 fp16 slopes (128 KB, L1-resident)
__device__ uint2  g_nodeTh[N_NODES_MAX * 32];   // per (node,lane): {s,v0,v1,v2} as 4 fp16
__device__ int    g_counts[N_NODES_MAX];
__device__ int    g_rowptr[N_NODES_MAX + 1];
__device__ int    g_cursor[N_NODES_MAX];
__device__ unsigned long long g_scan_state[MAX_SCAN_BLOCKS];  // (status<<32)|sum
__device__ uint4  g_erec[N_EDGES_MAX];          // 16B edge records sorted by receiver

__device__ __forceinline__ float swishf(float z) {
    return z / (1.0f + expf(-z));
}
__device__ __forceinline__ unsigned pack_h2(float a, float b) {
    half2 h = __floats2half2_rn(a, b);
    return *(unsigned*)&h;
}
__device__ __forceinline__ float2 unpack_h2(unsigned u) {
    return __half22float2(*(const half2*)&u);
}

// ---------------------------------------------------------------------------
// Fused preprocessing megakernel. Grid sections (all independent):
//   [0, TABLE_N)            : table build + fp16 pack (block b -> rows b, b+1)
//   [TABLE_N, TABLE_N+NT)   : node transpose + fp16 pack (8 nodes / block)
//   [TABLE_N+NT, ...)       : histogram of receivers (4 edges / thread)
// Block 0 also re-zeroes the scan state (graph replay safety).
// g_counts is zeroed by cudaMemsetAsync before this kernel.
// ---------------------------------------------------------------------------
__global__ void fused_pre_kernel(const float* __restrict__ w0,
                                 const float* __restrict__ w1,
                                 const float* __restrict__ w2,
                                 const float* __restrict__ nf,
                                 const int* __restrict__ receivers,
                                 int n_nodes, int E, int nt_blocks) {
    const int b = blockIdx.x;

    if (b == 0 && threadIdx.x < MAX_SCAN_BLOCKS)
        g_scan_state[threadIdx.x] = 0ULL;

    if (b < TABLE_N) {
        // ---- table build (rows b and min(b+1, TABLE_N-1)) + pack ----
        __shared__ float h0[2][64];
        __shared__ float h1[2][64];
        __shared__ float mix[2][128];
        const int half_i = threadIdx.x >> 7;         // 0 or 1
        const int t = threadIdx.x & 127;
        const int row = min(b + half_i, TABLE_N - 1);
        const float dx = (XMAX - XMIN) / (float)(TABLE_N - 1);
        const float x = XMIN + dx * (float)row;

        if (t < 64) h0[half_i][t] = swishf(x * w0[t]);
        __syncthreads();
        if (t < 64) {
            float acc = 0.0f;
#pragma unroll 8
            for (int i = 0; i < 64; i++) acc = fmaf(h0[half_i][i], w1[i * 64 + t], acc);
            h1[half_i][t] = swishf(acc * 0.125f);
        }
        __syncthreads();
        {
            float acc = 0.0f;
#pragma unroll 8
            for (int i = 0; i < 64; i++) acc = fmaf(h1[half_i][i], w2[i * 128 + t], acc);
            float m = acc * 0.125f * OUT_SCALE;
            if (t >= 32 && t < 64) m *= INV_SQRT3;   // tp_0e factor folded
            mix[half_i][t] = m;
        }
        __syncthreads();
        if (threadIdx.x < 32) {
            const int lane = threadIdx.x;
            float vs = mix[0][lane],      vt = mix[0][32 + lane];
            float vv = mix[0][64 + lane], vp = mix[0][96 + lane];
            float ds = mix[1][lane] - vs,      dt = mix[1][32 + lane] - vt;
            float dv = mix[1][64 + lane] - vv, dp = mix[1][96 + lane] - vp;
            uint4 u;
            u.x = pack_h2(vs, vt);
            u.y = pack_h2(vv, vp);
            u.z = pack_h2(ds, dt);
            u.w = pack_h2(dv, dp);
            g_tab[b * 32 + lane] = u;
        }
        return;
    }

    if (b < TABLE_N + nt_blocks) {
        // ---- node transpose + fp16 pack: {s, v0, v1, v2} ----
        const int wid  = threadIdx.x >> 5;
        const int lane = threadIdx.x & 31;
        const int node = (b - TABLE_N) * 8 + wid;
        if (node >= n_nodes) return;
        const float* r = nf + (size_t)node * NODE_ROW;
        float s  = __ldg(r + lane);
        float v0 = __ldg(r + 32 + 3 * lane);
        float v1 = __ldg(r + 33 + 3 * lane);
        float v2 = __ldg(r + 34 + 3 * lane);
        uint2 p;
        p.x = pack_h2(s, v0);
        p.y = pack_h2(v1, v2);
        g_nodeTh[(size_t)node * 32 + lane] = p;
        return;
    }

    // ---- histogram: 4 edges per thread, vectorized read ----
    const int idx = (b - TABLE_N - nt_blocks) * (256 * 4) + threadIdx.x * 4;
    if (idx + 3 < E) {
        int4 r4 = __ldg((const int4*)(receivers + idx));
        atomicAdd(&g_counts[r4.x], 1);
        atomicAdd(&g_counts[r4.y], 1);
        atomicAdd(&g_counts[r4.z], 1);
        atomicAdd(&g_counts[r4.w], 1);
    } else {
        for (int e = idx; e < E; e++) atomicAdd(&g_counts[receivers[e]], 1);
    }
}

// ---------------------------------------------------------------------------
// Single-pass exclusive scan with decoupled lookback (all blocks resident:
// grid <= 64 blocks << 148 SMs). Writes g_rowptr and g_cursor.
// ---------------------------------------------------------------------------
__global__ void scan_kernel(int n_nodes, int E) {
    __shared__ int s[SCAN_B];
    __shared__ int s_off;
    const int t = threadIdx.x;
    const int b = blockIdx.x;
    const int gid = b * SCAN_B + t;
    int v = (gid < n_nodes) ? g_counts[gid] : 0;
    s[t] = v;
    __syncthreads();
    for (int d = 1; d < SCAN_B; d <<= 1) {
        int x = (t >= d) ? s[t - d] : 0;
        __syncthreads();
        s[t] += x;
        __syncthreads();
    }
    const int total = s[SCAN_B - 1];

    if (b == 0) {
        if (t == 0) {
            s_off = 0;
            atomicExch(&g_scan_state[0], (2ULL << 32) | (unsigned)total);
        }
    } else {
        if (t == 0)
            atomicExch(&g_scan_state[b], (1ULL << 32) | (unsigned)total);
        if (t < 32) {
            int running = 0;
            int i = b - 1;
            while (true) {
                const int idx = i - t;
                unsigned status = 2u;
                int sum = 0;
                if (idx >= 0) {
                    unsigned long long st;
                    do { st = atomicAdd(&g_scan_state[idx], 0ULL); }
                    while ((st >> 32) == 0);
                    status = (unsigned)(st >> 32);
                    sum = (int)(unsigned)st;
                }
                const unsigned ball = __ballot_sync(0xffffffffu, status == 2u);
                const int firstInc = __ffs(ball) - 1;   // closest inclusive; -1 if none
                int contrib = (firstInc < 0 || t <= firstInc) ? sum : 0;
#pragma unroll
                for (int o = 16; o > 0; o >>= 1)
                    contrib += __shfl_down_sync(0xffffffffu, contrib, o);
                running += __shfl_sync(0xffffffffu, contrib, 0);
                if (firstInc >= 0) break;
                i -= 32;
            }
            if (t == 0) {
                s_off = running;
                atomicExch(&g_scan_state[b], (2ULL << 32) | (unsigned)(running + total));
            }
        }
    }
    __syncthreads();

    const int off = s_off;
    if (gid < n_nodes) {
        const int r = s[t] - v + off;
        g_rowptr[gid] = r;
        g_cursor[gid] = r;
    }
    if (gid == 0) g_rowptr[n_nodes] = E;
}

// ---------------------------------------------------------------------------
// Fused zero_rows + scatter (both depend only on scan; disjoint outputs).
// Section A [0, zr_blocks): zero output rows that will be RED targets or
//   never touched (segment crosses/abuts a chunk boundary, empty, or at E).
// Section B: payload scatter. Precomputes lerp (i0, frac); 16B record:
//   {h2(ea1.x,ea1.y), h2(ea1.z,f), sender, ((i0*32)<<16)|receiver}
// ---------------------------------------------------------------------------
__global__ void zero_scatter_kernel(const int* __restrict__ senders,
                                    const int* __restrict__ receivers,
                                    const float4* __restrict__ edge_attrs,
                                    float* __restrict__ out,
                                    int n_nodes, int E, int zr_blocks) {
    const int b = blockIdx.x;

    if (b < zr_blocks) {
        const int wid  = threadIdx.x >> 5;
        const int lane = threadIdx.x & 31;
        const int node = b * 8 + wid;
        if (node >= n_nodes) return;
        const int a  = __ldg(&g_rowptr[node]);
        const int bb = __ldg(&g_rowptr[node + 1]);
        const bool nz = (a == bb)
                     || ((a % CHUNK) == 0)
                     || ((bb % CHUNK) == 0)
                     || ((a / CHUNK) != ((bb - 1) / CHUNK))
                     || (bb == E);
        if (!nz) return;
        float* op = out + (size_t)node * OUT_ROW;
#pragma unroll
        for (int j = 0; j < 8; j++) op[32 * j + lane] = 0.0f;
        return;
    }

    const int e = (b - zr_blocks) * 256 + threadIdx.x;
    if (e < E) {
        const int r = __ldg(&receivers[e]);
        const int pos = atomicAdd(&g_cursor[r], 1);
        const float4 ea = __ldg(&edge_attrs[e]);
        const float inv_dx = (float)(TABLE_N - 1) / (XMAX - XMIN);
        float tt = (ea.x - XMIN) * inv_dx;
        tt = fminf(fmaxf(tt, 0.0f), (float)(TABLE_N - 1) - 1.0e-3f);
        const int i0 = (int)tt;
        const float f = tt - (float)i0;
        uint4 rec;
        rec.x = pack_h2(ea.y, ea.z);
        rec.y = pack_h2(ea.w, f);
        rec.z = (unsigned)__ldg(&senders[e]);
        rec.w = ((unsigned)(i0 * 32) << 16) | (unsigned)r;   // pre-shifted i0
        g_erec[pos] = rec;
    }
}

// ---------------------------------------------------------------------------
// Aggregate: each warp owns a fixed CHUNK of the receiver-sorted edge array
// (perfect balance; grid fits in ONE wave at 6 blocks/SM). Lane l owns
// channel l; receiver is warp-uniform. HFMA2 lerp. Interior segments ->
// plain STG; chunk-boundary segments -> RED onto pre-zeroed rows.
// ---------------------------------------------------------------------------
__device__ __forceinline__ void flush_red(float* __restrict__ out, int r, int lane,
                                          float a_s, float a_t,
                                          float av0, float av1, float av2,
                                          float ap0, float ap1, float ap2) {
    float* op = out + (size_t)r * OUT_ROW;
    asm volatile("red.global.add.f32 [%0], %1;" :: "l"(op + lane), "f"(a_s) : "memory");
    asm volatile("red.global.add.f32 [%0], %1;" :: "l"(op + 32 + lane), "f"(a_t) : "memory");
    asm volatile("red.global.add.f32 [%0], %1;" :: "l"(op + 64 + 3 * lane), "f"(av0) : "memory");
    asm volatile("red.global.add.f32 [%0], %1;" :: "l"(op + 65 + 3 * lane), "f"(av1) : "memory");
    asm volatile("red.global.add.f32 [%0], %1;" :: "l"(op + 66 + 3 * lane), "f"(av2) : "memory");
    asm volatile("red.global.add.f32 [%0], %1;" :: "l"(op + 160 + 3 * lane), "f"(ap0) : "memory");
    asm volatile("red.global.add.f32 [%0], %1;" :: "l"(op + 161 + 3 * lane), "f"(ap1) : "memory");
    asm volatile("red.global.add.f32 [%0], %1;" :: "l"(op + 162 + 3 * lane), "f"(ap2) : "memory");
}

__device__ __forceinline__ void flush_stg(float* __restrict__ out, int r, int lane,
                                          float a_s, float a_t,
                                          float av0, float av1, float av2,
                                          float ap0, float ap1, float ap2) {
    float* op = out + (size_t)r * OUT_ROW;
    op[lane]               = a_s;
    op[32 + lane]          = a_t;
    op[64  + 3 * lane]     = av0;
    op[65  + 3 * lane]     = av1;
    op[66  + 3 * lane]     = av2;
    op[160 + 3 * lane]     = ap0;
    op[161 + 3 * lane]     = ap1;
    op[162 + 3 * lane]     = ap2;
}

__global__ __launch_bounds__(256, 6)
void aggregate_kernel(float* __restrict__ out, int E) {
    const int wid  = threadIdx.x >> 5;
    const int lane = threadIdx.x & 31;
    const int base = (blockIdx.x * 8 + wid) * CHUNK;
    if (base >= E) return;
    const int lim = min(base + CHUNK, E);

    float a_s = 0.f, a_t = 0.f;
    float av0 = 0.f, av1 = 0.f, av2 = 0.f;
    float ap0 = 0.f, ap1 = 0.f, ap2 = 0.f;
    int cur_r = -1;
    int seg_interior = 0;   // 1 if current segment started strictly after base

    for (int i = base; i < lim; i++) {
        const uint4 R = __ldg(&g_erec[i]);         // 16B broadcast
        const float2 e01 = unpack_h2(R.x);         // {ea1x, ea1y}
        const half2 e2fh = *(const half2*)&R.y;    // {ea1z, f}
        const float ez = __low2float(e2fh);
        const half2 f2 = __half2half2(__high2half(e2fh));
        const int s     = (int)R.z;
        const int i0off = (int)(R.w >> 16);        // i0*32, pre-shifted
        const int r     = (int)(R.w & 0xFFFFu);

        if (r != cur_r) {
            if (cur_r >= 0) {
                if (seg_interior)
                    flush_stg(out, cur_r, lane, a_s, a_t, av0, av1, av2, ap0, ap1, ap2);
                else
                    flush_red(out, cur_r, lane, a_s, a_t, av0, av1, av2, ap0, ap1, ap2);
                a_s = a_t = 0.f;
                av0 = av1 = av2 = 0.f;
                ap0 = ap1 = ap2 = 0.f;
            }
            cur_r = r;
            seg_interior = (i > base);
        }

        const uint2 nfu = __ldg(&g_nodeTh[(size_t)s * 32 + lane]);
        const float2 sv  = unpack_h2(nfu.x);       // {s_e, v0}
        const float2 v12 = unpack_h2(nfu.y);       // {v1, v2}

        const uint4 tb = __ldg(&g_tab[i0off + lane]);
        // half2 lerp: m = val + slope * f  (2x HFMA2)
        const half2 m_st = __hfma2(*(const half2*)&tb.z, f2, *(const half2*)&tb.x);
        const half2 m_vp = __hfma2(*(const half2*)&tb.w, f2, *(const half2*)&tb.y);
        const float m_s = __low2float(m_st);
        const float m_t = __high2float(m_st);
        const float m_v = __low2float(m_vp);
        const float m_p = __high2float(m_vp);

        a_s = fmaf(sv.x, m_s, a_s);
        const float dot3 = fmaf(sv.y, e01.x, fmaf(v12.x, e01.y, v12.y * ez));
        a_t = fmaf(dot3, m_t, a_t);                // INV_SQRT3 folded into table
        av0 = fmaf(sv.y, m_v, av0);
        av1 = fmaf(v12.x, m_v, av1);
        av2 = fmaf(v12.y, m_v, av2);
        const float sp = sv.x * m_p;
        ap0 = fmaf(sp, e01.x, ap0);
        ap1 = fmaf(sp, e01.y, ap1);
        ap2 = fmaf(sp, ez, ap2);
    }

    // Last segment touches the chunk end: may continue into the next chunk.
    flush_red(out, cur_r, lane, a_s, a_t, av0, av1, av2, ap0, ap1, ap2);
}

// ---------------------------------------------------------------------------
// Launch
// ---------------------------------------------------------------------------
extern "C" void kernel_launch(void* const* d_in, const int* in_sizes, int n_in,
                              void* d_out, int out_size) {
    const float* node_feats = (const float*)d_in[0];
    const float* edge_attrs = (const float*)d_in[1];
    const int*   senders    = (const int*)d_in[2];
    const int*   receivers  = (const int*)d_in[3];
    const float* w0         = (const float*)d_in[4];
    const float* w1         = (const float*)d_in[5];
    const float* w2         = (const float*)d_in[6];
    float* out = (float*)d_out;
    const int E = in_sizes[1] / 4;          // edge_attrs is E x 4
    const int n_nodes = out_size / OUT_ROW; // output is n_nodes x 256
    const int nb = (n_nodes + SCAN_B - 1) / SCAN_B;   // <= 64 (all resident)
    const int nt_blocks = (n_nodes + 7) / 8;
    const int hist_blocks = (E + 1023) / 1024;
    const int zr_blocks = (n_nodes + 7) / 8;
    const int sc_blocks = (E + 255) / 256;
    const int nwarp = (E + CHUNK - 1) / CHUNK;

    void* counts_ptr = nullptr;
    cudaGetSymbolAddress(&counts_ptr, g_counts);
    cudaMemsetAsync(counts_ptr, 0, (size_t)n_nodes * sizeof(int));

    fused_pre_kernel<<<TABLE_N + nt_blocks + hist_blocks, 256>>>(
        w0, w1, w2, node_feats, receivers, n_nodes, E, nt_blocks);
    scan_kernel<<<nb, SCAN_B>>>(n_nodes, E);
    zero_scatter_kernel<<<zr_blocks + sc_blocks, 256>>>(
        senders, receivers, (const float4*)edge_attrs, out, n_nodes, E, zr_blocks);
    aggregate_kernel<<<(nwarp + 7) / 8, 256>>>(out, E);
}

// round 16
// speedup vs baseline: 1.0475x; 1.0475x over previous
#include <cuda_runtime.h>
#include <cuda_fp16.h>

#define N_NODES_MAX 50000
#define N_EDGES_MAX 800000
#define NODE_ROW 128          // 4*MUL floats per node
#define OUT_ROW 256           // output floats per node
#define TABLE_N 256
#define XMIN (-8.0f)
#define XMAX (8.0f)
#define INV_SQRT3 0.57735026918962576f
#define OUT_SCALE 0.25f       // 1/sqrt(16)
#define SCAN_B 1024
#define MAX_SCAN_BLOCKS 64
#define CHUNK 64              // edges per warp in aggregate (2-wave grid self-balances)

// ---- static device scratch (no allocations allowed) ----
__device__ uint4  g_tab[TABLE_N * 32];          // per (i0,lane): 4 fp16 vals + 4 fp16 slopes (128 KB, L1-resident)
__device__ uint2  g_nodeTh[N_NODES_MAX * 32];   // per (node,lane): {s,v0,v1,v2} as 4 fp16
__device__ int    g_counts[N_NODES_MAX];
__device__ int    g_rowptr[N_NODES_MAX + 1];
__device__ int    g_cursor[N_NODES_MAX];
__device__ unsigned long long g_scan_state[MAX_SCAN_BLOCKS];  // (status<<32)|sum
__device__ uint4  g_erec[N_EDGES_MAX];          // 16B edge records sorted by receiver

__device__ __forceinline__ float swishf(float z) {
    return z / (1.0f + expf(-z));
}
__device__ __forceinline__ unsigned pack_h2(float a, float b) {
    half2 h = __floats2half2_rn(a, b);
    return *(unsigned*)&h;
}
__device__ __forceinline__ float2 unpack_h2(unsigned u) {
    return __half22float2(*(const half2*)&u);
}

// ---------------------------------------------------------------------------
// Histogram kernel — FIRST on the critical path (scan waits only on this).
// 4 edges per thread, vectorized read. Block 0 re-zeroes scan state.
// g_counts zeroed by cudaMemsetAsync before this kernel.
// ---------------------------------------------------------------------------
__global__ void hist_kernel(const int* __restrict__ receivers, int E) {
    if (blockIdx.x == 0 && threadIdx.x < MAX_SCAN_BLOCKS)
        g_scan_state[threadIdx.x] = 0ULL;
    const int idx = blockIdx.x * (256 * 4) + threadIdx.x * 4;
    if (idx + 3 < E) {
        int4 r4 = __ldg((const int4*)(receivers + idx));
        atomicAdd(&g_counts[r4.x], 1);
        atomicAdd(&g_counts[r4.y], 1);
        atomicAdd(&g_counts[r4.z], 1);
        atomicAdd(&g_counts[r4.w], 1);
    } else {
        for (int e = idx; e < E; e++) atomicAdd(&g_counts[receivers[e]], 1);
    }
}

// ---------------------------------------------------------------------------
// Single-pass exclusive scan with decoupled lookback (all blocks resident:
// grid <= 64 blocks << 148 SMs). Writes g_rowptr and g_cursor.
// ---------------------------------------------------------------------------
__global__ void scan_kernel(int n_nodes, int E) {
    __shared__ int s[SCAN_B];
    __shared__ int s_off;
    const int t = threadIdx.x;
    const int b = blockIdx.x;
    const int gid = b * SCAN_B + t;
    int v = (gid < n_nodes) ? g_counts[gid] : 0;
    s[t] = v;
    __syncthreads();
    for (int d = 1; d < SCAN_B; d <<= 1) {
        int x = (t >= d) ? s[t - d] : 0;
        __syncthreads();
        s[t] += x;
        __syncthreads();
    }
    const int total = s[SCAN_B - 1];

    if (b == 0) {
        if (t == 0) {
            s_off = 0;
            atomicExch(&g_scan_state[0], (2ULL << 32) | (unsigned)total);
        }
    } else {
        if (t == 0)
            atomicExch(&g_scan_state[b], (1ULL << 32) | (unsigned)total);
        if (t < 32) {
            int running = 0;
            int i = b - 1;
            while (true) {
                const int idx = i - t;
                unsigned status = 2u;
                int sum = 0;
                if (idx >= 0) {
                    unsigned long long st;
                    do { st = atomicAdd(&g_scan_state[idx], 0ULL); }
                    while ((st >> 32) == 0);
                    status = (unsigned)(st >> 32);
                    sum = (int)(unsigned)st;
                }
                const unsigned ball = __ballot_sync(0xffffffffu, status == 2u);
                const int firstInc = __ffs(ball) - 1;   // closest inclusive; -1 if none
                int contrib = (firstInc < 0 || t <= firstInc) ? sum : 0;
#pragma unroll
                for (int o = 16; o > 0; o >>= 1)
                    contrib += __shfl_down_sync(0xffffffffu, contrib, o);
                running += __shfl_sync(0xffffffffu, contrib, 0);
                if (firstInc >= 0) break;
                i -= 32;
            }
            if (t == 0) {
                s_off = running;
                atomicExch(&g_scan_state[b], (2ULL << 32) | (unsigned)(running + total));
            }
        }
    }
    __syncthreads();

    const int off = s_off;
    if (gid < n_nodes) {
        const int r = s[t] - v + off;
        g_rowptr[gid] = r;
        g_cursor[gid] = r;
    }
    if (gid == 0) g_rowptr[n_nodes] = E;
}

// ---------------------------------------------------------------------------
// Fused prep kernel (everything between scan and aggregate; all sections
// mutually independent). Grid sections:
//   [0, TABLE_N)                   : mix table build + fp16 pack
//   [TABLE_N, +nt)                 : node transpose + fp16 pack
//   [TABLE_N+nt, +nt)              : zero RED-target / untouched output rows
//   [TABLE_N+2*nt, +sc)            : payload scatter (sorted by receiver)
// ---------------------------------------------------------------------------
__global__ void prep_kernel(const float* __restrict__ w0,
                            const float* __restrict__ w1,
                            const float* __restrict__ w2,
                            const float* __restrict__ nf,
                            const int* __restrict__ senders,
                            const int* __restrict__ receivers,
                            const float4* __restrict__ edge_attrs,
                            float* __restrict__ out,
                            int n_nodes, int E, int nt_blocks) {
    const int b = blockIdx.x;

    if (b < TABLE_N) {
        // ---- table build (rows b and min(b+1, TABLE_N-1)) + pack ----
        __shared__ float h0[2][64];
        __shared__ float h1[2][64];
        __shared__ float mix[2][128];
        const int half_i = threadIdx.x >> 7;         // 0 or 1
        const int t = threadIdx.x & 127;
        const int row = min(b + half_i, TABLE_N - 1);
        const float dx = (XMAX - XMIN) / (float)(TABLE_N - 1);
        const float x = XMIN + dx * (float)row;

        if (t < 64) h0[half_i][t] = swishf(x * w0[t]);
        __syncthreads();
        if (t < 64) {
            float acc = 0.0f;
#pragma unroll 8
            for (int i = 0; i < 64; i++) acc = fmaf(h0[half_i][i], w1[i * 64 + t], acc);
            h1[half_i][t] = swishf(acc * 0.125f);
        }
        __syncthreads();
        {
            float acc = 0.0f;
#pragma unroll 8
            for (int i = 0; i < 64; i++) acc = fmaf(h1[half_i][i], w2[i * 128 + t], acc);
            float m = acc * 0.125f * OUT_SCALE;
            if (t >= 32 && t < 64) m *= INV_SQRT3;   // tp_0e factor folded
            mix[half_i][t] = m;
        }
        __syncthreads();
        if (threadIdx.x < 32) {
            const int lane = threadIdx.x;
            float vs = mix[0][lane],      vt = mix[0][32 + lane];
            float vv = mix[0][64 + lane], vp = mix[0][96 + lane];
            float ds = mix[1][lane] - vs,      dt = mix[1][32 + lane] - vt;
            float dv = mix[1][64 + lane] - vv, dp = mix[1][96 + lane] - vp;
            uint4 u;
            u.x = pack_h2(vs, vt);
            u.y = pack_h2(vv, vp);
            u.z = pack_h2(ds, dt);
            u.w = pack_h2(dv, dp);
            g_tab[b * 32 + lane] = u;
        }
        return;
    }

    if (b < TABLE_N + nt_blocks) {
        // ---- node transpose + fp16 pack: {s, v0, v1, v2} ----
        const int wid  = threadIdx.x >> 5;
        const int lane = threadIdx.x & 31;
        const int node = (b - TABLE_N) * 8 + wid;
        if (node >= n_nodes) return;
        const float* r = nf + (size_t)node * NODE_ROW;
        float s  = __ldg(r + lane);
        float v0 = __ldg(r + 32 + 3 * lane);
        float v1 = __ldg(r + 33 + 3 * lane);
        float v2 = __ldg(r + 34 + 3 * lane);
        uint2 p;
        p.x = pack_h2(s, v0);
        p.y = pack_h2(v1, v2);
        g_nodeTh[(size_t)node * 32 + lane] = p;
        return;
    }

    if (b < TABLE_N + 2 * nt_blocks) {
        // ---- zero RED-target / untouched output rows ----
        const int wid  = threadIdx.x >> 5;
        const int lane = threadIdx.x & 31;
        const int node = (b - TABLE_N - nt_blocks) * 8 + wid;
        if (node >= n_nodes) return;
        const int a  = __ldg(&g_rowptr[node]);
        const int bb = __ldg(&g_rowptr[node + 1]);
        const bool nz = (a == bb)
                     || ((a % CHUNK) == 0)
                     || ((bb % CHUNK) == 0)
                     || ((a / CHUNK) != ((bb - 1) / CHUNK))
                     || (bb == E);
        if (!nz) return;
        float* op = out + (size_t)node * OUT_ROW;
#pragma unroll
        for (int j = 0; j < 8; j++) op[32 * j + lane] = 0.0f;
        return;
    }

    // ---- payload scatter: 16B record into receiver-sorted position ----
    const int e = (b - TABLE_N - 2 * nt_blocks) * 256 + threadIdx.x;
    if (e < E) {
        const int r = __ldg(&receivers[e]);
        const int pos = atomicAdd(&g_cursor[r], 1);
        const float4 ea = __ldg(&edge_attrs[e]);
        const float inv_dx = (float)(TABLE_N - 1) / (XMAX - XMIN);
        float tt = (ea.x - XMIN) * inv_dx;
        tt = fminf(fmaxf(tt, 0.0f), (float)(TABLE_N - 1) - 1.0e-3f);
        const int i0 = (int)tt;
        const float f = tt - (float)i0;
        uint4 rec;
        rec.x = pack_h2(ea.y, ea.z);
        rec.y = pack_h2(ea.w, f);
        rec.z = (unsigned)__ldg(&senders[e]);
        rec.w = ((unsigned)(i0 * 32) << 16) | (unsigned)r;   // pre-shifted i0
        g_erec[pos] = rec;
    }
}

// ---------------------------------------------------------------------------
// Aggregate (R13 configuration — local optimum): each warp owns a fixed
// CHUNK of the receiver-sorted edge array. Lane l owns channel l; receiver
// is warp-uniform. HFMA2 lerp. Interior segments -> plain STG; chunk-
// boundary segments -> RED onto pre-zeroed rows.
// ---------------------------------------------------------------------------
__device__ __forceinline__ void flush_red(float* __restrict__ out, int r, int lane,
                                          float a_s, float a_t,
                                          float av0, float av1, float av2,
                                          float ap0, float ap1, float ap2) {
    float* op = out + (size_t)r * OUT_ROW;
    asm volatile("red.global.add.f32 [%0], %1;" :: "l"(op + lane), "f"(a_s) : "memory");
    asm volatile("red.global.add.f32 [%0], %1;" :: "l"(op + 32 + lane), "f"(a_t) : "memory");
    asm volatile("red.global.add.f32 [%0], %1;" :: "l"(op + 64 + 3 * lane), "f"(av0) : "memory");
    asm volatile("red.global.add.f32 [%0], %1;" :: "l"(op + 65 + 3 * lane), "f"(av1) : "memory");
    asm volatile("red.global.add.f32 [%0], %1;" :: "l"(op + 66 + 3 * lane), "f"(av2) : "memory");
    asm volatile("red.global.add.f32 [%0], %1;" :: "l"(op + 160 + 3 * lane), "f"(ap0) : "memory");
    asm volatile("red.global.add.f32 [%0], %1;" :: "l"(op + 161 + 3 * lane), "f"(ap1) : "memory");
    asm volatile("red.global.add.f32 [%0], %1;" :: "l"(op + 162 + 3 * lane), "f"(ap2) : "memory");
}

__device__ __forceinline__ void flush_stg(float* __restrict__ out, int r, int lane,
                                          float a_s, float a_t,
                                          float av0, float av1, float av2,
                                          float ap0, float ap1, float ap2) {
    float* op = out + (size_t)r * OUT_ROW;
    op[lane]               = a_s;
    op[32 + lane]          = a_t;
    op[64  + 3 * lane]     = av0;
    op[65  + 3 * lane]     = av1;
    op[66  + 3 * lane]     = av2;
    op[160 + 3 * lane]     = ap0;
    op[161 + 3 * lane]     = ap1;
    op[162 + 3 * lane]     = ap2;
}

__global__ __launch_bounds__(256, 6)
void aggregate_kernel(float* __restrict__ out, int E) {
    const int wid  = threadIdx.x >> 5;
    const int lane = threadIdx.x & 31;
    const int base = (blockIdx.x * 8 + wid) * CHUNK;
    if (base >= E) return;
    const int lim = min(base + CHUNK, E);

    float a_s = 0.f, a_t = 0.f;
    float av0 = 0.f, av1 = 0.f, av2 = 0.f;
    float ap0 = 0.f, ap1 = 0.f, ap2 = 0.f;
    int cur_r = -1;
    int seg_interior = 0;   // 1 if current segment started strictly after base

    for (int i = base; i < lim; i++) {
        const uint4 R = __ldg(&g_erec[i]);         // 16B broadcast
        const float2 e01 = unpack_h2(R.x);         // {ea1x, ea1y}
        const half2 e2fh = *(const half2*)&R.y;    // {ea1z, f}
        const float ez = __low2float(e2fh);
        const half2 f2 = __half2half2(__high2half(e2fh));
        const int s     = (int)R.z;
        const int i0off = (int)(R.w >> 16);        // i0*32, pre-shifted
        const int r     = (int)(R.w & 0xFFFFu);

        if (r != cur_r) {
            if (cur_r >= 0) {
                if (seg_interior)
                    flush_stg(out, cur_r, lane, a_s, a_t, av0, av1, av2, ap0, ap1, ap2);
                else
                    flush_red(out, cur_r, lane, a_s, a_t, av0, av1, av2, ap0, ap1, ap2);
                a_s = a_t = 0.f;
                av0 = av1 = av2 = 0.f;
                ap0 = ap1 = ap2 = 0.f;
            }
            cur_r = r;
            seg_interior = (i > base);
        }

        const uint2 nfu = __ldg(&g_nodeTh[(size_t)s * 32 + lane]);
        const float2 sv  = unpack_h2(nfu.x);       // {s_e, v0}
        const float2 v12 = unpack_h2(nfu.y);       // {v1, v2}

        const uint4 tb = __ldg(&g_tab[i0off + lane]);
        // half2 lerp: m = val + slope * f  (2x HFMA2)
        const half2 m_st = __hfma2(*(const half2*)&tb.z, f2, *(const half2*)&tb.x);
        const half2 m_vp = __hfma2(*(const half2*)&tb.w, f2, *(const half2*)&tb.y);
        const float m_s = __low2float(m_st);
        const float m_t = __high2float(m_st);
        const float m_v = __low2float(m_vp);
        const float m_p = __high2float(m_vp);

        a_s = fmaf(sv.x, m_s, a_s);
        const float dot3 = fmaf(sv.y, e01.x, fmaf(v12.x, e01.y, v12.y * ez));
        a_t = fmaf(dot3, m_t, a_t);                // INV_SQRT3 folded into table
        av0 = fmaf(sv.y, m_v, av0);
        av1 = fmaf(v12.x, m_v, av1);
        av2 = fmaf(v12.y, m_v, av2);
        const float sp = sv.x * m_p;
        ap0 = fmaf(sp, e01.x, ap0);
        ap1 = fmaf(sp, e01.y, ap1);
        ap2 = fmaf(sp, ez, ap2);
    }

    // Last segment touches the chunk end: may continue into the next chunk.
    flush_red(out, cur_r, lane, a_s, a_t, av0, av1, av2, ap0, ap1, ap2);
}

// ---------------------------------------------------------------------------
// Launch
// ---------------------------------------------------------------------------
extern "C" void kernel_launch(void* const* d_in, const int* in_sizes, int n_in,
                              void* d_out, int out_size) {
    const float* node_feats = (const float*)d_in[0];
    const float* edge_attrs = (const float*)d_in[1];
    const int*   senders    = (const int*)d_in[2];
    const int*   receivers  = (const int*)d_in[3];
    const float* w0         = (const float*)d_in[4];
    const float* w1         = (const float*)d_in[5];
    const float* w2         = (const float*)d_in[6];
    float* out = (float*)d_out;
    const int E = in_sizes[1] / 4;          // edge_attrs is E x 4
    const int n_nodes = out_size / OUT_ROW; // output is n_nodes x 256
    const int nb = (n_nodes + SCAN_B - 1) / SCAN_B;   // <= 64 (all resident)
    const int nt_blocks = (n_nodes + 7) / 8;
    const int hist_blocks = (E + 1023) / 1024;
    const int sc_blocks = (E + 255) / 256;
    const int nwarp = (E + CHUNK - 1) / CHUNK;

    void* counts_ptr = nullptr;
    cudaGetSymbolAddress(&counts_ptr, g_counts);
    cudaMemsetAsync(counts_ptr, 0, (size_t)n_nodes * sizeof(int));

    hist_kernel<<<hist_blocks, 256>>>(receivers, E);
    scan_kernel<<<nb, SCAN_B>>>(n_nodes, E);
    prep_kernel<<<TABLE_N + 2 * nt_blocks + sc_blocks, 256>>>(
        w0, w1, w2, node_feats, senders, receivers,
        (const float4*)edge_attrs, out, n_nodes, E, nt_blocks);
    aggregate_kernel<<<(nwarp + 7) / 8, 256>>>(out, E);
}

// round 17
// speedup vs baseline: 1.0651x; 1.0169x over previous
#include <cuda_runtime.h>
#include <cuda_fp16.h>

#define N_NODES_MAX 50000
#define N_EDGES_MAX 800000
#define NODE_ROW 128          // 4*MUL floats per node
#define OUT_ROW 256           // output floats per node
#define TABLE_N 256
#define XMIN (-8.0f)
#define XMAX (8.0f)
#define INV_SQRT3 0.57735026918962576f
#define OUT_SCALE 0.25f       // 1/sqrt(16)
#define SCAN_B 1024
#define MAX_SCAN_BLOCKS 64
#define CHUNK 64              // edges per warp in aggregate

// ---- static device scratch (no allocations allowed) ----
__device__ uint4  g_tab[TABLE_N * 32];          // per (i0,lane): 4 fp16 vals + 4 fp16 slopes (128 KB, L1-resident)
__device__ uint2  g_nodeTh[N_NODES_MAX * 32];   // per (node,lane): {s,v0,v1,v2} as 4 fp16
__device__ int    g_counts[N_NODES_MAX];
__device__ int    g_rowptr[N_NODES_MAX + 1];
__device__ int    g_cursor[N_NODES_MAX];
__device__ unsigned long long g_scan_state[MAX_SCAN_BLOCKS];  // (status<<32)|sum
__device__ uint4  g_erec[N_EDGES_MAX];          // 16B edge records sorted by receiver

__device__ __forceinline__ float swishf(float z) {
    return z / (1.0f + expf(-z));
}
__device__ __forceinline__ unsigned pack_h2(float a, float b) {
    half2 h = __floats2half2_rn(a, b);
    return *(unsigned*)&h;
}
__device__ __forceinline__ float2 unpack_h2(unsigned u) {
    return __half22float2(*(const half2*)&u);
}

// ---------------------------------------------------------------------------
// Fused preprocessing megakernel. Grid sections (all independent):
//   [0, TABLE_N)            : table build + fp16 pack (block b -> rows b, b+1)
//   [TABLE_N, TABLE_N+NT)   : node transpose + fp16 pack (8 nodes / block)
//   [TABLE_N+NT, ...)       : histogram of receivers (4 edges / thread)
// Block 0 also re-zeroes the scan state (graph replay safety).
// g_counts is zeroed by cudaMemsetAsync before this kernel.
// ---------------------------------------------------------------------------
__global__ void fused_pre_kernel(const float* __restrict__ w0,
                                 const float* __restrict__ w1,
                                 const float* __restrict__ w2,
                                 const float* __restrict__ nf,
                                 const int* __restrict__ receivers,
                                 int n_nodes, int E, int nt_blocks) {
    const int b = blockIdx.x;

    if (b == 0 && threadIdx.x < MAX_SCAN_BLOCKS)
        g_scan_state[threadIdx.x] = 0ULL;

    if (b < TABLE_N) {
        // ---- table build (rows b and min(b+1, TABLE_N-1)) + pack ----
        __shared__ float h0[2][64];
        __shared__ float h1[2][64];
        __shared__ float mix[2][128];
        const int half_i = threadIdx.x >> 7;         // 0 or 1
        const int t = threadIdx.x & 127;
        const int row = min(b + half_i, TABLE_N - 1);
        const float dx = (XMAX - XMIN) / (float)(TABLE_N - 1);
        const float x = XMIN + dx * (float)row;

        if (t < 64) h0[half_i][t] = swishf(x * w0[t]);
        __syncthreads();
        if (t < 64) {
            float acc = 0.0f;
#pragma unroll 8
            for (int i = 0; i < 64; i++) acc = fmaf(h0[half_i][i], w1[i * 64 + t], acc);
            h1[half_i][t] = swishf(acc * 0.125f);
        }
        __syncthreads();
        {
            float acc = 0.0f;
#pragma unroll 8
            for (int i = 0; i < 64; i++) acc = fmaf(h1[half_i][i], w2[i * 128 + t], acc);
            float m = acc * 0.125f * OUT_SCALE;
            if (t >= 32 && t < 64) m *= INV_SQRT3;   // tp_0e factor folded
            mix[half_i][t] = m;
        }
        __syncthreads();
        if (threadIdx.x < 32) {
            const int lane = threadIdx.x;
            float vs = mix[0][lane],      vt = mix[0][32 + lane];
            float vv = mix[0][64 + lane], vp = mix[0][96 + lane];
            float ds = mix[1][lane] - vs,      dt = mix[1][32 + lane] - vt;
            float dv = mix[1][64 + lane] - vv, dp = mix[1][96 + lane] - vp;
            uint4 u;
            u.x = pack_h2(vs, vt);
            u.y = pack_h2(vv, vp);
            u.z = pack_h2(ds, dt);
            u.w = pack_h2(dv, dp);
            g_tab[b * 32 + lane] = u;
        }
        return;
    }

    if (b < TABLE_N + nt_blocks) {
        // ---- node transpose + fp16 pack: {s, v0, v1, v2} ----
        const int wid  = threadIdx.x >> 5;
        const int lane = threadIdx.x & 31;
        const int node = (b - TABLE_N) * 8 + wid;
        if (node >= n_nodes) return;
        const float* r = nf + (size_t)node * NODE_ROW;
        float s  = __ldg(r + lane);
        float v0 = __ldg(r + 32 + 3 * lane);
        float v1 = __ldg(r + 33 + 3 * lane);
        float v2 = __ldg(r + 34 + 3 * lane);
        uint2 p;
        p.x = pack_h2(s, v0);
        p.y = pack_h2(v1, v2);
        g_nodeTh[(size_t)node * 32 + lane] = p;
        return;
    }

    // ---- histogram: 4 edges per thread, vectorized read ----
    const int idx = (b - TABLE_N - nt_blocks) * (256 * 4) + threadIdx.x * 4;
    if (idx + 3 < E) {
        int4 r4 = __ldg((const int4*)(receivers + idx));
        atomicAdd(&g_counts[r4.x], 1);
        atomicAdd(&g_counts[r4.y], 1);
        atomicAdd(&g_counts[r4.z], 1);
        atomicAdd(&g_counts[r4.w], 1);
    } else {
        for (int e = idx; e < E; e++) atomicAdd(&g_counts[receivers[e]], 1);
    }
}

// ---------------------------------------------------------------------------
// Single-pass exclusive scan with decoupled lookback (all blocks resident:
// grid <= 64 blocks << 148 SMs). Writes g_rowptr and g_cursor.
// ---------------------------------------------------------------------------
__global__ void scan_kernel(int n_nodes, int E) {
    __shared__ int s[SCAN_B];
    __shared__ int s_off;
    const int t = threadIdx.x;
    const int b = blockIdx.x;
    const int gid = b * SCAN_B + t;
    int v = (gid < n_nodes) ? g_counts[gid] : 0;
    s[t] = v;
    __syncthreads();
    for (int d = 1; d < SCAN_B; d <<= 1) {
        int x = (t >= d) ? s[t - d] : 0;
        __syncthreads();
        s[t] += x;
        __syncthreads();
    }
    const int total = s[SCAN_B - 1];

    if (b == 0) {
        if (t == 0) {
            s_off = 0;
            atomicExch(&g_scan_state[0], (2ULL << 32) | (unsigned)total);
        }
    } else {
        if (t == 0)
            atomicExch(&g_scan_state[b], (1ULL << 32) | (unsigned)total);
        if (t < 32) {
            int running = 0;
            int i = b - 1;
            while (true) {
                const int idx = i - t;
                unsigned status = 2u;
                int sum = 0;
                if (idx >= 0) {
                    unsigned long long st;
                    do { st = atomicAdd(&g_scan_state[idx], 0ULL); }
                    while ((st >> 32) == 0);
                    status = (unsigned)(st >> 32);
                    sum = (int)(unsigned)st;
                }
                const unsigned ball = __ballot_sync(0xffffffffu, status == 2u);
                const int firstInc = __ffs(ball) - 1;   // closest inclusive; -1 if none
                int contrib = (firstInc < 0 || t <= firstInc) ? sum : 0;
#pragma unroll
                for (int o = 16; o > 0; o >>= 1)
                    contrib += __shfl_down_sync(0xffffffffu, contrib, o);
                running += __shfl_sync(0xffffffffu, contrib, 0);
                if (firstInc >= 0) break;
                i -= 32;
            }
            if (t == 0) {
                s_off = running;
                atomicExch(&g_scan_state[b], (2ULL << 32) | (unsigned)(running + total));
            }
        }
    }
    __syncthreads();

    const int off = s_off;
    if (gid < n_nodes) {
        const int r = s[t] - v + off;
        g_rowptr[gid] = r;
        g_cursor[gid] = r;
    }
    if (gid == 0) g_rowptr[n_nodes] = E;
}

// ---------------------------------------------------------------------------
// Fused zero_rows + scatter (both depend only on scan; disjoint outputs).
// Section A [0, zr_blocks): zero output rows that will be RED targets or
//   never touched (segment crosses/abuts a chunk boundary, empty, or at E).
// Section B: payload scatter. Precomputes lerp (i0, frac); 16B record:
//   {h2(ea1.x,ea1.y), h2(ea1.z,f), sender, ((i0*32)<<16)|receiver}
// ---------------------------------------------------------------------------
__global__ void zero_scatter_kernel(const int* __restrict__ senders,
                                    const int* __restrict__ receivers,
                                    const float4* __restrict__ edge_attrs,
                                    float* __restrict__ out,
                                    int n_nodes, int E, int zr_blocks) {
    const int b = blockIdx.x;

    if (b < zr_blocks) {
        const int wid  = threadIdx.x >> 5;
        const int lane = threadIdx.x & 31;
        const int node = b * 8 + wid;
        if (node >= n_nodes) return;
        const int a  = __ldg(&g_rowptr[node]);
        const int bb = __ldg(&g_rowptr[node + 1]);
        const bool nz = (a == bb)
                     || ((a % CHUNK) == 0)
                     || ((bb % CHUNK) == 0)
                     || ((a / CHUNK) != ((bb - 1) / CHUNK))
                     || (bb == E);
        if (!nz) return;
        float* op = out + (size_t)node * OUT_ROW;
#pragma unroll
        for (int j = 0; j < 8; j++) op[32 * j + lane] = 0.0f;
        return;
    }

    const int e = (b - zr_blocks) * 256 + threadIdx.x;
    if (e < E) {
        const int r = __ldg(&receivers[e]);
        const int pos = atomicAdd(&g_cursor[r], 1);
        const float4 ea = __ldg(&edge_attrs[e]);
        const float inv_dx = (float)(TABLE_N - 1) / (XMAX - XMIN);
        float tt = (ea.x - XMIN) * inv_dx;
        tt = fminf(fmaxf(tt, 0.0f), (float)(TABLE_N - 1) - 1.0e-3f);
        const int i0 = (int)tt;
        const float f = tt - (float)i0;
        uint4 rec;
        rec.x = pack_h2(ea.y, ea.z);
        rec.y = pack_h2(ea.w, f);
        rec.z = (unsigned)__ldg(&senders[e]);
        rec.w = ((unsigned)(i0 * 32) << 16) | (unsigned)r;   // pre-shifted i0
        g_erec[pos] = rec;
    }
}

// ---------------------------------------------------------------------------
// Aggregate: each warp owns a fixed CHUNK of the receiver-sorted edge array
// (perfect balance). Lane l owns channel l; receiver is warp-uniform.
// HFMA2 lerp. Interior segments -> plain STG; chunk-boundary segments ->
// RED onto pre-zeroed rows. __launch_bounds__(256,7) targets 36 regs ->
// 7 blocks/SM (87.5% theoretical occupancy) for better latency hiding.
// ---------------------------------------------------------------------------
__device__ __forceinline__ void flush_red(float* __restrict__ out, int r, int lane,
                                          float a_s, float a_t,
                                          float av0, float av1, float av2,
                                          float ap0, float ap1, float ap2) {
    float* op = out + (size_t)r * OUT_ROW;
    asm volatile("red.global.add.f32 [%0], %1;" :: "l"(op + lane), "f"(a_s) : "memory");
    asm volatile("red.global.add.f32 [%0], %1;" :: "l"(op + 32 + lane), "f"(a_t) : "memory");
    asm volatile("red.global.add.f32 [%0], %1;" :: "l"(op + 64 + 3 * lane), "f"(av0) : "memory");
    asm volatile("red.global.add.f32 [%0], %1;" :: "l"(op + 65 + 3 * lane), "f"(av1) : "memory");
    asm volatile("red.global.add.f32 [%0], %1;" :: "l"(op + 66 + 3 * lane), "f"(av2) : "memory");
    asm volatile("red.global.add.f32 [%0], %1;" :: "l"(op + 160 + 3 * lane), "f"(ap0) : "memory");
    asm volatile("red.global.add.f32 [%0], %1;" :: "l"(op + 161 + 3 * lane), "f"(ap1) : "memory");
    asm volatile("red.global.add.f32 [%0], %1;" :: "l"(op + 162 + 3 * lane), "f"(ap2) : "memory");
}

__device__ __forceinline__ void flush_stg(float* __restrict__ out, int r, int lane,
                                          float a_s, float a_t,
                                          float av0, float av1, float av2,
                                          float ap0, float ap1, float ap2) {
    float* op = out + (size_t)r * OUT_ROW;
    op[lane]               = a_s;
    op[32 + lane]          = a_t;
    op[64  + 3 * lane]     = av0;
    op[65  + 3 * lane]     = av1;
    op[66  + 3 * lane]     = av2;
    op[160 + 3 * lane]     = ap0;
    op[161 + 3 * lane]     = ap1;
    op[162 + 3 * lane]     = ap2;
}

__global__ __launch_bounds__(256, 7)
void aggregate_kernel(float* __restrict__ out, int E) {
    const int wid  = threadIdx.x >> 5;
    const int lane = threadIdx.x & 31;
    const int base = (blockIdx.x * 8 + wid) * CHUNK;
    if (base >= E) return;
    const int lim = min(base + CHUNK, E);

    float a_s = 0.f, a_t = 0.f;
    float av0 = 0.f, av1 = 0.f, av2 = 0.f;
    float ap0 = 0.f, ap1 = 0.f, ap2 = 0.f;
    int cur_r = -1;
    int seg_interior = 0;   // 1 if current segment started strictly after base

    for (int i = base; i < lim; i++) {
        const uint4 R = __ldg(&g_erec[i]);         // 16B broadcast
        const float2 e01 = unpack_h2(R.x);         // {ea1x, ea1y}
        const half2 e2fh = *(const half2*)&R.y;    // {ea1z, f}
        const float ez = __low2float(e2fh);
        const half2 f2 = __half2half2(__high2half(e2fh));
        const int s     = (int)R.z;
        const int i0off = (int)(R.w >> 16);        // i0*32, pre-shifted
        const int r     = (int)(R.w & 0xFFFFu);

        if (r != cur_r) {
            if (cur_r >= 0) {
                if (seg_interior)
                    flush_stg(out, cur_r, lane, a_s, a_t, av0, av1, av2, ap0, ap1, ap2);
                else
                    flush_red(out, cur_r, lane, a_s, a_t, av0, av1, av2, ap0, ap1, ap2);
                a_s = a_t = 0.f;
                av0 = av1 = av2 = 0.f;
                ap0 = ap1 = ap2 = 0.f;
            }
            cur_r = r;
            seg_interior = (i > base);
        }

        const uint2 nfu = __ldg(&g_nodeTh[(size_t)s * 32 + lane]);
        const float2 sv  = unpack_h2(nfu.x);       // {s_e, v0}
        const float2 v12 = unpack_h2(nfu.y);       // {v1, v2}

        const uint4 tb = __ldg(&g_tab[i0off + lane]);
        // half2 lerp: m = val + slope * f  (2x HFMA2)
        const half2 m_st = __hfma2(*(const half2*)&tb.z, f2, *(const half2*)&tb.x);
        const half2 m_vp = __hfma2(*(const half2*)&tb.w, f2, *(const half2*)&tb.y);
        const float m_s = __low2float(m_st);
        const float m_t = __high2float(m_st);
        const float m_v = __low2float(m_vp);
        const float m_p = __high2float(m_vp);

        a_s = fmaf(sv.x, m_s, a_s);
        const float dot3 = fmaf(sv.y, e01.x, fmaf(v12.x, e01.y, v12.y * ez));
        a_t = fmaf(dot3, m_t, a_t);                // INV_SQRT3 folded into table
        av0 = fmaf(sv.y, m_v, av0);
        av1 = fmaf(v12.x, m_v, av1);
        av2 = fmaf(v12.y, m_v, av2);
        const float sp = sv.x * m_p;
        ap0 = fmaf(sp, e01.x, ap0);
        ap1 = fmaf(sp, e01.y, ap1);
        ap2 = fmaf(sp, ez, ap2);
    }

    // Last segment touches the chunk end: may continue into the next chunk.
    flush_red(out, cur_r, lane, a_s, a_t, av0, av1, av2, ap0, ap1, ap2);
}

// ---------------------------------------------------------------------------
// Launch
// ---------------------------------------------------------------------------
extern "C" void kernel_launch(void* const* d_in, const int* in_sizes, int n_in,
                              void* d_out, int out_size) {
    const float* node_feats = (const float*)d_in[0];
    const float* edge_attrs = (const float*)d_in[1];
    const int*   senders    = (const int*)d_in[2];
    const int*   receivers  = (const int*)d_in[3];
    const float* w0         = (const float*)d_in[4];
    const float* w1         = (const float*)d_in[5];
    const float* w2         = (const float*)d_in[6];
    float* out = (float*)d_out;
    const int E = in_sizes[1] / 4;          // edge_attrs is E x 4
    const int n_nodes = out_size / OUT_ROW; // output is n_nodes x 256
    const int nb = (n_nodes + SCAN_B - 1) / SCAN_B;   // <= 64 (all resident)
    const int nt_blocks = (n_nodes + 7) / 8;
    const int hist_blocks = (E + 1023) / 1024;
    const int zr_blocks = (n_nodes + 7) / 8;
    const int sc_blocks = (E + 255) / 256;
    const int nwarp = (E + CHUNK - 1) / CHUNK;

    void* counts_ptr = nullptr;
    cudaGetSymbolAddress(&counts_ptr, g_counts);
    cudaMemsetAsync(counts_ptr, 0, (size_t)n_nodes * sizeof(int));

    fused_pre_kernel<<<TABLE_N + nt_blocks + hist_blocks, 256>>>(
        w0, w1, w2, node_feats, receivers, n_nodes, E, nt_blocks);
    scan_kernel<<<nb, SCAN_B>>>(n_nodes, E);
    zero_scatter_kernel<<<zr_blocks + sc_blocks, 256>>>(
        senders, receivers, (const float4*)edge_attrs, out, n_nodes, E, zr_blocks);
    aggregate_kernel<<<(nwarp + 7) / 8, 256>>>(out, E);
}